// round 16
// baseline (speedup 1.0000x reference)
#include <cuda_runtime.h>
#include <cuda_fp16.h>
#include <math.h>

#define NN 512
#define FF 64
#define SS 5
#define TT 32
#define NC 16       // sender chunks per receiver
#define CHUNK (NN/NC)   // 32
#define TSZ 32      // sender tile size == CHUNK
#define NPTS 2048   // wj table points
#define RMAX 16.0f

// -------- device scratch (no allocations allowed) --------
__device__ float  g_x0v[NN*FF];          // layer0: x0 only
__device__ float4 g_xv[NN*FF];           // layer1: {x0, x1x, x1y, x1z}
__device__ float4 g_t0a[NPTS*FF];        // L0 table: {v0,v1,v2, h2(s0,s1)}
__device__ __half g_t0s2[NPTS*FF];       // L0 table: s2
__device__ float4 g_t5a[NPTS*FF];        // L1 table: {v0,v1,v2,v3}
__device__ float4 g_t5b[NPTS*FF];        // L1 table: {v4, h2(s0,s1), h2(s2,s3), h2(s4,0)}
__device__ float  g_Apart[NC*NN*9*FF];   // partial segment sums (18.9MB, L2-resident)
__device__ float  g_pos[NN*3];           // current positions

__device__ __forceinline__ float2 h2f(float bits) {
    __half2 h; unsigned u = __float_as_uint(bits);
    h = *(__half2*)&u;
    return __half22float2(h);
}
__device__ __forceinline__ float packh2(float a, float b) {
    __half2 h = __floats2half2_rn(a, b);
    return __uint_as_float(*(unsigned*)&h);
}

// -------- fused: wj tables (both layers) + embed/layer0-linear --------
#define NB_TAB (2*(NPTS/8))
__global__ void k_prep(const float* __restrict__ We1, const float* __restrict__ be1,
                       const float* __restrict__ We2,
                       const float* __restrict__ pos_in, const int* __restrict__ nodef,
                       const float* __restrict__ te, const float* __restrict__ W_embed,
                       const float* __restrict__ b_embed, const float* __restrict__ Wl0) {
    int f = threadIdx.x, ty = threadIdx.y;
    int bx = blockIdx.x;
    if (bx < NB_TAB) {
        __shared__ float sW[32*320];    // We2 repacked: [k][f*5+j]
        __shared__ float sHe[9][32];
        int layer = bx / (NPTS/8);
        int p0 = (bx % (NPTS/8)) * 8;
        int tid = ty*64 + f;
        const float hstep = RMAX / (float)(NPTS-1);
        const float* We2l = We2 + layer*32*384;
        const float* We1l = We1 + layer*32;
        const float* be1l = be1 + layer*32;

        for (int idx = tid; idx < 32*320; idx += 512) {
            int k = idx / 320, cc = idx % 320;
            sW[idx] = We2l[k*384 + (cc/5)*6 + (cc%5)];
        }
        for (int idx = tid; idx < 9*32; idx += 512) {
            int row = idx >> 5, k = idx & 31;
            int p = p0 + row; if (p > NPTS-1) p = NPTS-1;
            float x = fmaf((float)p * hstep, We1l[k], be1l[k]);
            sHe[row][k] = x / (1.0f + expf(-x));
        }
        __syncthreads();

        float va[5] = {0,0,0,0,0}, vb[5] = {0,0,0,0,0};
        #pragma unroll 4
        for (int k = 0; k < 32; k++) {
            float hA = sHe[ty][k], hB = sHe[ty+1][k];
            const float* w = &sW[k*320 + f*5];
            #pragma unroll
            for (int j = 0; j < 5; j++) {
                va[j] = fmaf(hA, w[j], va[j]);
                vb[j] = fmaf(hB, w[j], vb[j]);
            }
        }
        int ti = (p0 + ty)*FF + f;
        if (layer == 0) {
            g_t0a[ti] = make_float4(va[0], va[1], va[2],
                                    packh2(vb[0]-va[0], vb[1]-va[1]));
            g_t0s2[ti] = __float2half(vb[2]-va[2]);
        } else {
            g_t5a[ti] = make_float4(va[0], va[1], va[2], va[3]);
            g_t5b[ti] = make_float4(va[4],
                                    packh2(vb[0]-va[0], vb[1]-va[1]),
                                    packh2(vb[2]-va[2], vb[3]-va[3]),
                                    packh2(vb[4]-va[4], 0.f));
        }
    } else {
        __shared__ float sH[8][FF];
        int n = (bx - NB_TAB)*8 + ty;
        if (f < 3) g_pos[n*3+f] = pos_in[n*3+f];
        int sp = nodef[n] - 1;
        float h = W_embed[sp*FF + f] + b_embed[f];
        #pragma unroll
        for (int t = 0; t < TT; t++) h = fmaf(te[t], W_embed[(SS+t)*FF + f], h);
        sH[ty][f] = h;
        __syncthreads();
        float a0 = 0.f;
        #pragma unroll 8
        for (int g = 0; g < FF; g++) a0 = fmaf(sH[ty][g], Wl0[g*FF + f], a0);
        g_x0v[n*FF + f] = a0;
    }
}

// -------- edge kernel: 2 receivers per block, one 32-sender tile --------
// Receivers 2*bx and 2*bx+1 share the chunk: xv/x0 loaded ONCE per pair,
// two independent accumulator chains per thread (ILP for latency hiding).
template<int NJ>
__global__ void __launch_bounds__(64) k_edge() {
    const int r0 = blockIdx.x*2, c = blockIdx.y, f = threadIdx.x;
    __shared__ float sY1[2][TSZ][3];
    __shared__ float sY2[2][TSZ][5];
    __shared__ int   sIdx[2][TSZ];
    __shared__ float sFrac[2][TSZ];
    __shared__ float sVal[2][TSZ];

    const int base = c * CHUNK;
    {   // geometry: warp 0 -> receiver r0, warp 1 -> receiver r0+1
        int rp = f >> 5, ls = f & 31;
        int rr = r0 + rp;
        const float prx = g_pos[rr*3+0], pry = g_pos[rr*3+1], prz = g_pos[rr*3+2];
        const float tscale = (float)(NPTS-1) / RMAX;
        int s = base + ls;
        float vx = prx - g_pos[s*3+0];
        float vy = pry - g_pos[s*3+1];
        float vz = prz - g_pos[s*3+2];
        float r2 = vx*vx + vy*vy + vz*vz;
        int ok = (s != rr);
        float inv = ok ? rsqrtf(r2) : 0.0f;
        float rl = r2 * inv;
        float ux = vx*inv, uy = vy*inv, uz = vz*inv;
        float t = fminf(rl * tscale, (float)NPTS - 1.001f);
        int i = (int)t;
        sIdx[rp][ls]  = i;
        sFrac[rp][ls] = t - (float)i;
        sVal[rp][ls]  = ok ? 1.0f : 0.0f;
        const float s3  = 1.7320508075688772f;
        const float s5h = 0.5f * 2.2360679774997896f;
        const float s15 = 3.8729833462074170f;
        const float s15h = 0.5f * 3.8729833462074170f;
        sY1[rp][ls][0] = s3*ux; sY1[rp][ls][1] = s3*uy; sY1[rp][ls][2] = s3*uz;
        sY2[rp][ls][0] = s15*ux*uy;
        sY2[rp][ls][1] = s15*uy*uz;
        sY2[rp][ls][2] = s5h*(3.f*uz*uz - 1.f);
        sY2[rp][ls][3] = s15*ux*uz;
        sY2[rp][ls][4] = s15h*(ux*ux - uy*uy);
    }
    __syncthreads();

    float acc0[9], acc1[9];
    #pragma unroll
    for (int ch = 0; ch < 9; ch++) { acc0[ch] = 0.f; acc1[ch] = 0.f; }

    #pragma unroll 2
    for (int sl = 0; sl < TSZ; sl++) {
        int s = base + sl;
        int i0 = sIdx[0][sl],  i1 = sIdx[1][sl];
        float fr0 = sFrac[0][sl], fr1 = sFrac[1][sl];
        float val0 = sVal[0][sl], val1 = sVal[1][sl];

        if (NJ > 3) {
            float4 xv = g_xv[s*FF + f];            // shared by both receivers
            float4 A0 = g_t5a[i0*FF + f];
            float4 B0 = g_t5b[i0*FF + f];
            float4 A1 = g_t5a[i1*FF + f];
            float4 B1 = g_t5b[i1*FF + f];

            // receiver 0
            {
                float2 s01 = h2f(B0.y), s23 = h2f(B0.z), s4p = h2f(B0.w);
                float wj0 = fmaf(fr0, s01.x, A0.x);
                float wj1 = fmaf(fr0, s01.y, A0.y);
                float wj2 = fmaf(fr0, s23.x, A0.z);
                float wj3 = fmaf(fr0, s23.y, A0.w);
                float wj4 = fmaf(fr0, s4p.x, B0.x);
                float a0v = xv.x * val0;
                float a1x = xv.y * val0, a1y = xv.z * val0, a1z = xv.w * val0;
                float Y1x = sY1[0][sl][0], Y1y = sY1[0][sl][1], Y1z = sY1[0][sl][2];
                acc0[0] = fmaf(wj0, a0v, acc0[0]);
                float w1a = wj1 * a0v;
                acc0[1] = fmaf(w1a, Y1x, acc0[1]);
                acc0[2] = fmaf(w1a, Y1y, acc0[2]);
                acc0[3] = fmaf(w1a, Y1z, acc0[3]);
                float w2a = wj2 * a0v;
                acc0[4] = fmaf(w2a, sY2[0][sl][0], acc0[4]);
                acc0[5] = fmaf(w2a, sY2[0][sl][1], acc0[5]);
                acc0[6] = fmaf(w2a, sY2[0][sl][2], acc0[6]);
                acc0[7] = fmaf(w2a, sY2[0][sl][3], acc0[7]);
                acc0[8] = fmaf(w2a, sY2[0][sl][4], acc0[8]);
                float d1 = a1x*Y1x + a1y*Y1y + a1z*Y1z;
                acc0[0] = fmaf(wj3, d1, acc0[0]);
                acc0[1] = fmaf(wj4, a1y*Y1z - a1z*Y1y, acc0[1]);
                acc0[2] = fmaf(wj4, a1z*Y1x - a1x*Y1z, acc0[2]);
                acc0[3] = fmaf(wj4, a1x*Y1y - a1y*Y1x, acc0[3]);
            }
            // receiver 1
            {
                float2 s01 = h2f(B1.y), s23 = h2f(B1.z), s4p = h2f(B1.w);
                float wj0 = fmaf(fr1, s01.x, A1.x);
                float wj1 = fmaf(fr1, s01.y, A1.y);
                float wj2 = fmaf(fr1, s23.x, A1.z);
                float wj3 = fmaf(fr1, s23.y, A1.w);
                float wj4 = fmaf(fr1, s4p.x, B1.x);
                float a0v = xv.x * val1;
                float a1x = xv.y * val1, a1y = xv.z * val1, a1z = xv.w * val1;
                float Y1x = sY1[1][sl][0], Y1y = sY1[1][sl][1], Y1z = sY1[1][sl][2];
                acc1[0] = fmaf(wj0, a0v, acc1[0]);
                float w1a = wj1 * a0v;
                acc1[1] = fmaf(w1a, Y1x, acc1[1]);
                acc1[2] = fmaf(w1a, Y1y, acc1[2]);
                acc1[3] = fmaf(w1a, Y1z, acc1[3]);
                float w2a = wj2 * a0v;
                acc1[4] = fmaf(w2a, sY2[1][sl][0], acc1[4]);
                acc1[5] = fmaf(w2a, sY2[1][sl][1], acc1[5]);
                acc1[6] = fmaf(w2a, sY2[1][sl][2], acc1[6]);
                acc1[7] = fmaf(w2a, sY2[1][sl][3], acc1[7]);
                acc1[8] = fmaf(w2a, sY2[1][sl][4], acc1[8]);
                float d1 = a1x*Y1x + a1y*Y1y + a1z*Y1z;
                acc1[0] = fmaf(wj3, d1, acc1[0]);
                acc1[1] = fmaf(wj4, a1y*Y1z - a1z*Y1y, acc1[1]);
                acc1[2] = fmaf(wj4, a1z*Y1x - a1x*Y1z, acc1[2]);
                acc1[3] = fmaf(wj4, a1x*Y1y - a1y*Y1x, acc1[3]);
            }
        } else {
            float x0 = g_x0v[s*FF + f];            // shared by both receivers
            float4 A0 = g_t0a[i0*FF + f];
            float4 A1 = g_t0a[i1*FF + f];
            float s2_0 = __half2float(g_t0s2[i0*FF + f]);
            float s2_1 = __half2float(g_t0s2[i1*FF + f]);
            // receiver 0
            {
                float2 s01 = h2f(A0.w);
                float wj0 = fmaf(fr0, s01.x, A0.x);
                float wj1 = fmaf(fr0, s01.y, A0.y);
                float wj2 = fmaf(fr0, s2_0,  A0.z);
                float a0v = x0 * val0;
                acc0[0] = fmaf(wj0, a0v, acc0[0]);
                float w1a = wj1 * a0v;
                acc0[1] = fmaf(w1a, sY1[0][sl][0], acc0[1]);
                acc0[2] = fmaf(w1a, sY1[0][sl][1], acc0[2]);
                acc0[3] = fmaf(w1a, sY1[0][sl][2], acc0[3]);
                float w2a = wj2 * a0v;
                acc0[4] = fmaf(w2a, sY2[0][sl][0], acc0[4]);
                acc0[5] = fmaf(w2a, sY2[0][sl][1], acc0[5]);
                acc0[6] = fmaf(w2a, sY2[0][sl][2], acc0[6]);
                acc0[7] = fmaf(w2a, sY2[0][sl][3], acc0[7]);
                acc0[8] = fmaf(w2a, sY2[0][sl][4], acc0[8]);
            }
            // receiver 1
            {
                float2 s01 = h2f(A1.w);
                float wj0 = fmaf(fr1, s01.x, A1.x);
                float wj1 = fmaf(fr1, s01.y, A1.y);
                float wj2 = fmaf(fr1, s2_1,  A1.z);
                float a0v = x0 * val1;
                acc1[0] = fmaf(wj0, a0v, acc1[0]);
                float w1a = wj1 * a0v;
                acc1[1] = fmaf(w1a, sY1[1][sl][0], acc1[1]);
                acc1[2] = fmaf(w1a, sY1[1][sl][1], acc1[2]);
                acc1[3] = fmaf(w1a, sY1[1][sl][2], acc1[3]);
                float w2a = wj2 * a0v;
                acc1[4] = fmaf(w2a, sY2[1][sl][0], acc1[4]);
                acc1[5] = fmaf(w2a, sY2[1][sl][1], acc1[5]);
                acc1[6] = fmaf(w2a, sY2[1][sl][2], acc1[6]);
                acc1[7] = fmaf(w2a, sY2[1][sl][3], acc1[7]);
                acc1[8] = fmaf(w2a, sY2[1][sl][4], acc1[8]);
            }
        }
    }
    #pragma unroll
    for (int ch = 0; ch < 9; ch++) {
        g_Apart[((c*NN + r0    )*9 + ch)*FF + f] = acc0[ch];
        g_Apart[((c*NN + r0 + 1)*9 + ch)*FF + f] = acc1[ch];
    }
}

// -------- node update: one node / block, ty-parallel reduction --------
template<bool DO_LIN>
__global__ void k_node(const int* __restrict__ nodef,
                       const float* __restrict__ Wp0, const float* __restrict__ Wp1,
                       const float* __restrict__ Wr1, const float* __restrict__ br1,
                       const float* __restrict__ Wr2g, const float* __restrict__ WlinNext,
                       const float* __restrict__ pos_in, float* __restrict__ out) {
    int ty = threadIdx.y, f = threadIdx.x;
    int n = blockIdx.x;

    __shared__ float sA[4][9][FF];
    {
        float P[9];
        #pragma unroll
        for (int ch = 0; ch < 9; ch++) P[ch] = 0.f;
        #pragma unroll
        for (int cc = 0; cc < NC/4; cc++) {
            int c = ty*(NC/4) + cc;
            #pragma unroll
            for (int ch = 0; ch < 9; ch++)
                P[ch] += g_Apart[((c*NN + n)*9 + ch)*FF + f];
        }
        #pragma unroll
        for (int ch = 0; ch < 9; ch++) sA[ty][ch][f] = P[ch];
    }
    __syncthreads();

    __shared__ float sO[FF];
    __shared__ float sV[3][FF];
    __shared__ float sH[FF];
    __shared__ float sRed[3][FF];

    if (ty == 0) {
        float A[9];
        #pragma unroll
        for (int ch = 0; ch < 9; ch++)
            A[ch] = (sA[0][ch][f] + sA[1][ch][f] + sA[2][ch][f] + sA[3][ch][f])
                    * (1.0f/511.0f);
        float A0 = A[0];
        float n1 = A[1]*A[1] + A[2]*A[2] + A[3]*A[3];
        float n2 = A[4]*A[4] + A[5]*A[5] + A[6]*A[6] + A[7]*A[7] + A[8]*A[8];
        int sp = nodef[n] - 1;
        const float* w0 = Wp0 + (sp*FF + f)*6;
        float A02 = A0*A0;
        float out0 = w0[0]*A0 + w0[1]*A02 + w0[2]*A02*A0
                   + w0[3]*n1 + w0[4]*n2 + w0[5]*A0*n1;
        const float* w1 = Wp1 + (sp*FF + f)*3;
        float gp = w1[0] + w1[1]*A0 + w1[2]*A02;
        sO[f] = out0;
        sV[0][f] = gp*A[1]; sV[1][f] = gp*A[2]; sV[2][f] = gp*A[3];
    }
    __syncthreads();

    if (ty == 1 && DO_LIN) {
        float a0 = 0.f, a1x = 0.f, a1y = 0.f, a1z = 0.f;
        #pragma unroll 8
        for (int g = 0; g < FF; g++) {
            float wa = WlinNext[g*FF + f];
            float wb = WlinNext[FF*FF + g*FF + f];
            a0  = fmaf(sO[g],    wa, a0);
            a1x = fmaf(sV[0][g], wb, a1x);
            a1y = fmaf(sV[1][g], wb, a1y);
            a1z = fmaf(sV[2][g], wb, a1z);
        }
        g_xv[n*FF + f] = make_float4(a0, a1x, a1y, a1z);
    }
    if (ty == 0) {
        float hx = br1[f];
        #pragma unroll 8
        for (int g = 0; g < FF; g++) hx = fmaf(sO[g], Wr1[g*FF + f], hx);
        sH[f] = hx / (1.0f + expf(-hx));
    }
    __syncthreads();
    if (ty == 0) {
        float gate = 0.f;
        #pragma unroll 8
        for (int m = 0; m < FF; m++) gate = fmaf(sH[m], Wr2g[m*FF + f], gate);
        sRed[0][f] = gate*sV[0][f];
        sRed[1][f] = gate*sV[1][f];
        sRed[2][f] = gate*sV[2][f];
    }
    __syncthreads();
    if (ty == 0 && f < 3) {
        float v = 0.f;
        for (int g = 0; g < FF; g++) v += sRed[f][g];
        if (DO_LIN) {
            g_pos[n*3 + f] += v;   // deterministic: one thread per component
        } else {
            out[n*3 + f] = g_pos[n*3 + f] + v - pos_in[n*3 + f];
        }
    }
}

extern "C" void kernel_launch(void* const* d_in, const int* in_sizes, int n_in,
                              void* d_out, int out_size) {
    const float* positions = (const float*)d_in[0];
    const int*   nodef     = (const int*)  d_in[1];
    const float* te        = (const float*)d_in[2];
    // d_in[3]/[4] = senders/receivers: fully connected, structure used directly
    const float* W_embed   = (const float*)d_in[5];
    const float* b_embed   = (const float*)d_in[6];
    const float* W_lin     = (const float*)d_in[7];
    const float* W_e1      = (const float*)d_in[8];
    const float* b_e1      = (const float*)d_in[9];
    const float* W_e2      = (const float*)d_in[10];
    const float* Wp0       = (const float*)d_in[11];
    const float* Wp1       = (const float*)d_in[12];
    const float* Wr1       = (const float*)d_in[13];
    const float* br1       = (const float*)d_in[14];
    // d_in[15] = Wr2s: unused by the reference
    const float* Wr2g      = (const float*)d_in[16];
    float* out = (float*)d_out;

    dim3 b4(64, 4), b8(64, 8);

    k_prep<<<NB_TAB + NN/8, b8>>>(W_e1, b_e1, W_e2,
                                  positions, nodef, te, W_embed, b_embed, W_lin);

    // layer 0 (s1 == 0 -> only j in {0,1,2})
    k_edge<3><<<dim3(NN/2, NC), 64>>>();
    k_node<true><<<NN, b4>>>(nodef, Wp0, Wp1, Wr1, br1, Wr2g,
                             W_lin + 3*FF*FF, positions, out);

    // layer 1 (j in {0..4}; j==5 multiplies an identically-zero term)
    k_edge<5><<<dim3(NN/2, NC), 64>>>();
    k_node<false><<<NN, b4>>>(nodef, Wp0 + SS*FF*6, Wp1 + SS*FF*3,
                              Wr1 + FF*FF, br1 + FF, Wr2g + FF*FF,
                              nullptr, positions, out);
}

// round 17
// speedup vs baseline: 1.3183x; 1.3183x over previous
#include <cuda_runtime.h>
#include <cuda_fp16.h>
#include <math.h>

#define NN 512
#define FF 64
#define SS 5
#define TT 32
#define NC 16       // sender chunks per receiver
#define CHUNK (NN/NC)   // 32
#define TSZ 32      // sender tile size == CHUNK
#define NPTS 1024   // wj table points
#define RMAX 16.0f

// -------- device scratch (no allocations allowed) --------
__device__ float  g_x0v[NN*FF];          // layer0: x0 only
__device__ float4 g_xv[NN*FF];           // layer1: {x0, x1x, x1y, x1z}
__device__ float4 g_t0a[NPTS*FF];        // L0 table: {v0,v1,v2, h2(s0,s1)}
__device__ __half g_t0s2[NPTS*FF];       // L0 table: s2
__device__ float4 g_t5a[NPTS*FF];        // L1 table: {v0,v1,v2,v3}
__device__ float4 g_t5b[NPTS*FF];        // L1 table: {v4, h2(s0,s1), h2(s2,s3), h2(s4,0)}
__device__ float  g_Apart[NC*NN*9*FF];   // partial segment sums (18.9MB, L2-resident)
__device__ float  g_pos[NN*3];           // current positions

__device__ __forceinline__ float2 h2f(float bits) {
    __half2 h; unsigned u = __float_as_uint(bits);
    h = *(__half2*)&u;
    return __half22float2(h);
}
__device__ __forceinline__ float packh2(float a, float b) {
    __half2 h = __floats2half2_rn(a, b);
    return __uint_as_float(*(unsigned*)&h);
}

// -------- fused: wj tables (both layers) + embed/layer0-linear --------
#define NB_TAB (2*(NPTS/8))
__global__ void k_prep(const float* __restrict__ We1, const float* __restrict__ be1,
                       const float* __restrict__ We2,
                       const float* __restrict__ pos_in, const int* __restrict__ nodef,
                       const float* __restrict__ te, const float* __restrict__ W_embed,
                       const float* __restrict__ b_embed, const float* __restrict__ Wl0) {
    int f = threadIdx.x, ty = threadIdx.y;
    int bx = blockIdx.x;
    if (bx < NB_TAB) {
        __shared__ float sW[32*320];    // We2 repacked: [k][f*5+j]
        __shared__ float sHe[9][32];
        int layer = bx / (NPTS/8);
        int p0 = (bx % (NPTS/8)) * 8;
        int tid = ty*64 + f;
        const float hstep = RMAX / (float)(NPTS-1);
        const float* We2l = We2 + layer*32*384;
        const float* We1l = We1 + layer*32;
        const float* be1l = be1 + layer*32;

        // repack We2 -> sW without div/mod: thread (ty,f) covers k=ty*4..+3, col f
        #pragma unroll
        for (int kk = 0; kk < 4; kk++) {
            int k = ty*4 + kk;
            const float* src = We2l + k*384 + f*6;
            float* dst = &sW[k*320 + f*5];
            #pragma unroll
            for (int j = 0; j < 5; j++) dst[j] = src[j];
        }
        for (int idx = tid; idx < 9*32; idx += 512) {
            int row = idx >> 5, k = idx & 31;
            int p = p0 + row; if (p > NPTS-1) p = NPTS-1;
            float x = fmaf((float)p * hstep, We1l[k], be1l[k]);
            sHe[row][k] = x / (1.0f + expf(-x));
        }
        __syncthreads();

        float va[5] = {0,0,0,0,0}, vb[5] = {0,0,0,0,0};
        #pragma unroll 4
        for (int k = 0; k < 32; k++) {
            float hA = sHe[ty][k], hB = sHe[ty+1][k];
            const float* w = &sW[k*320 + f*5];
            #pragma unroll
            for (int j = 0; j < 5; j++) {
                va[j] = fmaf(hA, w[j], va[j]);
                vb[j] = fmaf(hB, w[j], vb[j]);
            }
        }
        int ti = (p0 + ty)*FF + f;
        if (layer == 0) {
            g_t0a[ti] = make_float4(va[0], va[1], va[2],
                                    packh2(vb[0]-va[0], vb[1]-va[1]));
            g_t0s2[ti] = __float2half(vb[2]-va[2]);
        } else {
            g_t5a[ti] = make_float4(va[0], va[1], va[2], va[3]);
            g_t5b[ti] = make_float4(va[4],
                                    packh2(vb[0]-va[0], vb[1]-va[1]),
                                    packh2(vb[2]-va[2], vb[3]-va[3]),
                                    packh2(vb[4]-va[4], 0.f));
        }
    } else {
        __shared__ float sH[8][FF];
        int n = (bx - NB_TAB)*8 + ty;
        if (f < 3) g_pos[n*3+f] = pos_in[n*3+f];
        int sp = nodef[n] - 1;
        float h = W_embed[sp*FF + f] + b_embed[f];
        #pragma unroll
        for (int t = 0; t < TT; t++) h = fmaf(te[t], W_embed[(SS+t)*FF + f], h);
        sH[ty][f] = h;
        __syncthreads();
        float a0 = 0.f;
        #pragma unroll 8
        for (int g = 0; g < FF; g++) a0 = fmaf(sH[ty][g], Wl0[g*FF + f], a0);
        g_x0v[n*FF + f] = a0;
    }
}

// -------- edge kernel: single 32-sender tile per block (R13 shape) --------
template<int NJ>
__global__ void __launch_bounds__(64) k_edge() {
    const int r = blockIdx.x, c = blockIdx.y, f = threadIdx.x;
    __shared__ float sY1[TSZ][3];
    __shared__ float sY2[TSZ][5];
    __shared__ int   sIdx[TSZ];
    __shared__ float sFrac[TSZ];
    __shared__ float sVal[TSZ];

    const int base = c * CHUNK;
    if (f < TSZ) {
        const float prx = g_pos[r*3+0], pry = g_pos[r*3+1], prz = g_pos[r*3+2];
        const float tscale = (float)(NPTS-1) / RMAX;
        int s = base + f;
        float vx = prx - g_pos[s*3+0];
        float vy = pry - g_pos[s*3+1];
        float vz = prz - g_pos[s*3+2];
        float r2 = vx*vx + vy*vy + vz*vz;
        int ok = (s != r);
        float inv = ok ? rsqrtf(r2) : 0.0f;
        float rl = r2 * inv;
        float ux = vx*inv, uy = vy*inv, uz = vz*inv;
        float t = fminf(rl * tscale, (float)NPTS - 1.001f);
        int i = (int)t;
        sIdx[f]  = i;
        sFrac[f] = t - (float)i;
        sVal[f]  = ok ? 1.0f : 0.0f;
        const float s3  = 1.7320508075688772f;
        const float s5h = 0.5f * 2.2360679774997896f;
        const float s15 = 3.8729833462074170f;
        const float s15h = 0.5f * 3.8729833462074170f;
        sY1[f][0] = s3*ux; sY1[f][1] = s3*uy; sY1[f][2] = s3*uz;
        sY2[f][0] = s15*ux*uy;
        sY2[f][1] = s15*uy*uz;
        sY2[f][2] = s5h*(3.f*uz*uz - 1.f);
        sY2[f][3] = s15*ux*uz;
        sY2[f][4] = s15h*(ux*ux - uy*uy);
    }
    __syncthreads();

    float acc[9];
    #pragma unroll
    for (int ch = 0; ch < 9; ch++) acc[ch] = 0.f;

    #pragma unroll 4
    for (int sl = 0; sl < TSZ; sl++) {
        int s = base + sl;
        int i = sIdx[sl];
        float fr = sFrac[sl], val = sVal[sl];
        int ti = i*FF + f;

        float wj0, wj1, wj2, wj3 = 0.f, wj4 = 0.f;
        float a0v, a1x = 0.f, a1y = 0.f, a1z = 0.f;
        if (NJ > 3) {
            float4 A = g_t5a[ti];
            float4 B = g_t5b[ti];
            float2 s01 = h2f(B.y);
            float2 s23 = h2f(B.z);
            float2 s4p = h2f(B.w);
            wj0 = fmaf(fr, s01.x, A.x);
            wj1 = fmaf(fr, s01.y, A.y);
            wj2 = fmaf(fr, s23.x, A.z);
            wj3 = fmaf(fr, s23.y, A.w);
            wj4 = fmaf(fr, s4p.x, B.x);
            float4 xv = g_xv[s*FF + f];
            a0v = xv.x * val;
            a1x = xv.y * val; a1y = xv.z * val; a1z = xv.w * val;
        } else {
            float4 A = g_t0a[ti];
            float2 s01 = h2f(A.w);
            float s2 = __half2float(g_t0s2[ti]);
            wj0 = fmaf(fr, s01.x, A.x);
            wj1 = fmaf(fr, s01.y, A.y);
            wj2 = fmaf(fr, s2,    A.z);
            a0v = g_x0v[s*FF + f] * val;
        }

        float Y1x = sY1[sl][0], Y1y = sY1[sl][1], Y1z = sY1[sl][2];
        acc[0] = fmaf(wj0, a0v, acc[0]);
        float w1a = wj1 * a0v;
        acc[1] = fmaf(w1a, Y1x, acc[1]);
        acc[2] = fmaf(w1a, Y1y, acc[2]);
        acc[3] = fmaf(w1a, Y1z, acc[3]);
        float w2a = wj2 * a0v;
        acc[4] = fmaf(w2a, sY2[sl][0], acc[4]);
        acc[5] = fmaf(w2a, sY2[sl][1], acc[5]);
        acc[6] = fmaf(w2a, sY2[sl][2], acc[6]);
        acc[7] = fmaf(w2a, sY2[sl][3], acc[7]);
        acc[8] = fmaf(w2a, sY2[sl][4], acc[8]);
        if (NJ > 3) {
            float d1 = a1x*Y1x + a1y*Y1y + a1z*Y1z;
            acc[0] = fmaf(wj3, d1, acc[0]);
            float crx = a1y*Y1z - a1z*Y1y;
            float cry = a1z*Y1x - a1x*Y1z;
            float crz = a1x*Y1y - a1y*Y1x;
            acc[1] = fmaf(wj4, crx, acc[1]);
            acc[2] = fmaf(wj4, cry, acc[2]);
            acc[3] = fmaf(wj4, crz, acc[3]);
        }
    }
    #pragma unroll
    for (int ch = 0; ch < 9; ch++)
        g_Apart[((c*NN + r)*9 + ch)*FF + f] = acc[ch];
}

// -------- node update: one node / block, ty-parallel reduction --------
template<bool DO_LIN>
__global__ void k_node(const int* __restrict__ nodef,
                       const float* __restrict__ Wp0, const float* __restrict__ Wp1,
                       const float* __restrict__ Wr1, const float* __restrict__ br1,
                       const float* __restrict__ Wr2g, const float* __restrict__ WlinNext,
                       const float* __restrict__ pos_in, float* __restrict__ out) {
    int ty = threadIdx.y, f = threadIdx.x;
    int n = blockIdx.x;

    __shared__ float sA[4][9][FF];
    {
        float P[9];
        #pragma unroll
        for (int ch = 0; ch < 9; ch++) P[ch] = 0.f;
        #pragma unroll
        for (int cc = 0; cc < NC/4; cc++) {
            int c = ty*(NC/4) + cc;
            #pragma unroll
            for (int ch = 0; ch < 9; ch++)
                P[ch] += g_Apart[((c*NN + n)*9 + ch)*FF + f];
        }
        #pragma unroll
        for (int ch = 0; ch < 9; ch++) sA[ty][ch][f] = P[ch];
    }
    __syncthreads();

    __shared__ float sO[FF];
    __shared__ float sV[3][FF];
    __shared__ float sH[FF];
    __shared__ float sRed[3][FF];

    if (ty == 0) {
        float A[9];
        #pragma unroll
        for (int ch = 0; ch < 9; ch++)
            A[ch] = (sA[0][ch][f] + sA[1][ch][f] + sA[2][ch][f] + sA[3][ch][f])
                    * (1.0f/511.0f);
        float A0 = A[0];
        float n1 = A[1]*A[1] + A[2]*A[2] + A[3]*A[3];
        float n2 = A[4]*A[4] + A[5]*A[5] + A[6]*A[6] + A[7]*A[7] + A[8]*A[8];
        int sp = nodef[n] - 1;
        const float* w0 = Wp0 + (sp*FF + f)*6;
        float A02 = A0*A0;
        float out0 = w0[0]*A0 + w0[1]*A02 + w0[2]*A02*A0
                   + w0[3]*n1 + w0[4]*n2 + w0[5]*A0*n1;
        const float* w1 = Wp1 + (sp*FF + f)*3;
        float gp = w1[0] + w1[1]*A0 + w1[2]*A02;
        sO[f] = out0;
        sV[0][f] = gp*A[1]; sV[1][f] = gp*A[2]; sV[2][f] = gp*A[3];
    }
    __syncthreads();

    if (ty == 1 && DO_LIN) {
        float a0 = 0.f, a1x = 0.f, a1y = 0.f, a1z = 0.f;
        #pragma unroll 8
        for (int g = 0; g < FF; g++) {
            float wa = WlinNext[g*FF + f];
            float wb = WlinNext[FF*FF + g*FF + f];
            a0  = fmaf(sO[g],    wa, a0);
            a1x = fmaf(sV[0][g], wb, a1x);
            a1y = fmaf(sV[1][g], wb, a1y);
            a1z = fmaf(sV[2][g], wb, a1z);
        }
        g_xv[n*FF + f] = make_float4(a0, a1x, a1y, a1z);
    }
    if (ty == 0) {
        float hx = br1[f];
        #pragma unroll 8
        for (int g = 0; g < FF; g++) hx = fmaf(sO[g], Wr1[g*FF + f], hx);
        sH[f] = hx / (1.0f + expf(-hx));
    }
    __syncthreads();
    if (ty == 0) {
        float gate = 0.f;
        #pragma unroll 8
        for (int m = 0; m < FF; m++) gate = fmaf(sH[m], Wr2g[m*FF + f], gate);
        sRed[0][f] = gate*sV[0][f];
        sRed[1][f] = gate*sV[1][f];
        sRed[2][f] = gate*sV[2][f];
    }
    __syncthreads();
    if (ty == 0 && f < 3) {
        float v = 0.f;
        for (int g = 0; g < FF; g++) v += sRed[f][g];
        if (DO_LIN) {
            g_pos[n*3 + f] += v;   // deterministic: one thread per component
        } else {
            out[n*3 + f] = g_pos[n*3 + f] + v - pos_in[n*3 + f];
        }
    }
}

extern "C" void kernel_launch(void* const* d_in, const int* in_sizes, int n_in,
                              void* d_out, int out_size) {
    const float* positions = (const float*)d_in[0];
    const int*   nodef     = (const int*)  d_in[1];
    const float* te        = (const float*)d_in[2];
    // d_in[3]/[4] = senders/receivers: fully connected, structure used directly
    const float* W_embed   = (const float*)d_in[5];
    const float* b_embed   = (const float*)d_in[6];
    const float* W_lin     = (const float*)d_in[7];
    const float* W_e1      = (const float*)d_in[8];
    const float* b_e1      = (const float*)d_in[9];
    const float* W_e2      = (const float*)d_in[10];
    const float* Wp0       = (const float*)d_in[11];
    const float* Wp1       = (const float*)d_in[12];
    const float* Wr1       = (const float*)d_in[13];
    const float* br1       = (const float*)d_in[14];
    // d_in[15] = Wr2s: unused by the reference
    const float* Wr2g      = (const float*)d_in[16];
    float* out = (float*)d_out;

    dim3 b4(64, 4), b8(64, 8);

    k_prep<<<NB_TAB + NN/8, b8>>>(W_e1, b_e1, W_e2,
                                  positions, nodef, te, W_embed, b_embed, W_lin);

    // layer 0 (s1 == 0 -> only j in {0,1,2})
    k_edge<3><<<dim3(NN, NC), 64>>>();
    k_node<true><<<NN, b4>>>(nodef, Wp0, Wp1, Wr1, br1, Wr2g,
                             W_lin + 3*FF*FF, positions, out);

    // layer 1 (j in {0..4}; j==5 multiplies an identically-zero term)
    k_edge<5><<<dim3(NN, NC), 64>>>();
    k_node<false><<<NN, b4>>>(nodef, Wp0 + SS*FF*6, Wp1 + SS*FF*3,
                              Wr1 + FF*FF, br1 + FF, Wr2g + FF*FF,
                              nullptr, positions, out);
}